// round 16
// baseline (speedup 1.0000x reference)
#include <cuda_runtime.h>

// ---------------------------------------------------------------------------
// TensoRF slim renderer, v15 — v8 champion + L1::no_allocate corner loads.
//  ONE variable changed vs the 269.1us v8: the 3 random-access corner texel
//  loads use ld.global.nc.L1::no_allocate so the zero-reuse 34MB corner
//  stream cannot evict the 115KB line textures from L1D; the 6 tap loads/pt
//  (high reuse) keep normal __ldg and should now be ~100% L1 hits.
//  Everything else identical: interleaved per-plane loads+math, 4-row packed
//  weight bank (row 3 = sigma ones), 6-shuffle butterfly reduce, smem
//  product scan, block rgb reduce.
// ---------------------------------------------------------------------------

#define MAXG  320
#define MAXHW (MAXG * MAXG)

__device__ float4 g_tex[3ull * MAXHW * 8];   // [i][p][8 float4] texel = 128B
__device__ float4 g_ltex[3 * MAXG * 8];      // [i][g][8 float4]

typedef unsigned long long ull;

__device__ __forceinline__ ull f2pk(float a, float b) {
    ull r; asm("mov.b64 %0,{%1,%2};" : "=l"(r) : "f"(a), "f"(b)); return r;
}
__device__ __forceinline__ float2 f2un(ull v) {
    float2 r; asm("mov.b64 {%0,%1},%2;" : "=f"(r.x), "=f"(r.y) : "l"(v)); return r;
}
__device__ __forceinline__ ull fma2(ull a, ull b, ull c) {
    ull r; asm("fma.rn.f32x2 %0,%1,%2,%3;" : "=l"(r) : "l"(a), "l"(b), "l"(c)); return r;
}
__device__ __forceinline__ ull mul2(ull a, ull b) {
    ull r; asm("mul.rn.f32x2 %0,%1,%2;" : "=l"(r) : "l"(a), "l"(b)); return r;
}
// streaming load: no L1 allocation (random-access corner texels, zero reuse)
__device__ __forceinline__ ulonglong2 ldg_na(const ulonglong2* p) {
    ulonglong2 v;
    asm("ld.global.nc.L1::no_allocate.v2.u64 {%0,%1}, [%2];"
        : "=l"(v.x), "=l"(v.y) : "l"(p));
    return v;
}

// ---------------- prep: interleave channels into 128B texels ----------------
__global__ void prep_kernel(const float* __restrict__ dp, const float* __restrict__ ap,
                            const float* __restrict__ dl, const float* __restrict__ al,
                            const float* __restrict__ denw, int G) {
    __shared__ float tile[32][129];
    int HW  = G * G;
    int ntp = (HW + 127) >> 7;
    int ntl = (G + 127) >> 7;
    int b = blockIdx.x;
    if (b < 3 * ntp) {
        int i = b / ntp, t = b - i * ntp;
        int p0 = t << 7;
        int np = min(128, HW - p0);
        for (int idx = threadIdx.x; idx < 32 * 128; idx += blockDim.x) {
            int ch = idx >> 7, p = idx & 127;
            float v = 0.f;
            if (p < np)
                v = (ch < 8) ? dp[(size_t)(i * 8 + ch) * HW + p0 + p]
                             : ap[(size_t)(i * 24 + ch - 8) * HW + p0 + p];
            tile[ch][p] = v;
        }
        __syncthreads();
        float* dst = (float*)(g_tex + ((size_t)i * MAXHW + p0) * 8);
        for (int idx = threadIdx.x; idx < np * 32; idx += blockDim.x) {
            int p = idx >> 5, ch = idx & 31;
            dst[idx] = tile[ch][p];
        }
    } else {
        b -= 3 * ntp;
        int i = b / ntl, t = b - i * ntl;
        int g0 = t << 7;
        int ng = min(128, G - g0);
        for (int idx = threadIdx.x; idx < 32 * 128; idx += blockDim.x) {
            int ch = idx >> 7, g = idx & 127;
            float v = 0.f;
            if (g < ng) {
                if (ch < 8) v = dl[(i * 8 + ch) * G + g0 + g] * denw[i * 8 + ch];
                else        v = al[(i * 24 + ch - 8) * G + g0 + g];
            }
            tile[ch][g] = v;
        }
        __syncthreads();
        float* dst = (float*)(g_ltex + ((size_t)i * MAXG + g0) * 8);
        for (int idx = threadIdx.x; idx < ng * 32; idx += blockDim.x) {
            int g = idx >> 5, ch = idx & 31;
            dst[idx] = tile[ch][g];
        }
    }
}

// ---------------- render ----------------
struct S1D { int i0, i1; float w; };

__device__ __forceinline__ S1D samp1d(float c, int G) {
    float f  = (c + 1.0f) * 0.5f * (float)(G - 1);
    float ff = floorf(f);
    S1D r;
    r.w = f - ff;                 // frac from UNclipped floor (matches ref)
    int i0 = (int)ff;
    i0 = min(max(i0, 0), G - 1);
    r.i0 = i0;
    r.i1 = min(i0 + 1, G - 1);
    return r;
}

__global__ __launch_bounds__(256, 3)
void render_kernel(const float* __restrict__ xyz,
                   const float* __restrict__ zvals,
                   const float* __restrict__ appw,
                   const float* __restrict__ aabb,
                   float* __restrict__ out,
                   int Ns, int G) {
    __shared__ float4 s_setA[256 * 3];  // per-pt per-plane (A, T, sxw, syw)
    __shared__ float4 s_setB[256];      // per-pt: stw x3
    __shared__ float  s_out[256 * 4];   // q0,q1,q2,sigma per point
    __shared__ float  s_z[256];
    __shared__ float  s_A[256];
    __shared__ float  s_B[256];
    __shared__ float  s_part[24];

    const int r      = blockIdx.x;
    const int tid    = threadIdx.x;
    const int lane   = tid & 31;
    const int wrp    = tid >> 5;
    const int corner = lane >> 3;       // 0..3
    const int slot   = lane & 7;        // 0..7 (f4 index within texel)
    const bool pc1   = (corner & 1) != 0;
    const bool pc2   = (corner & 2) != 0;
    const bool isApp = (slot >= 2);
    const int  G8    = G * 8;           // y-step in f4 units

    // packed weights: rows 0-2 = appw (zeros on density lanes);
    // row 3 = sigma row: ones on density lanes, zeros on app lanes.
    ull WA[4][3], WB[4][3];
    {
        const ull ones = f2pk(1.f, 1.f);
#pragma unroll
        for (int rr = 0; rr < 3; rr++)
#pragma unroll
            for (int i = 0; i < 3; i++) {
                if (isApp) {
                    float4 w = *(const float4*)(appw + rr * 72 + i * 24 + (slot - 2) * 4);
                    WA[rr][i] = f2pk(w.x, w.y);
                    WB[rr][i] = f2pk(w.z, w.w);
                } else {
                    WA[rr][i] = 0ull; WB[rr][i] = 0ull;
                }
            }
#pragma unroll
        for (int i = 0; i < 3; i++) {
            WA[3][i] = isApp ? 0ull : ones;
            WB[3][i] = isApp ? 0ull : ones;
        }
    }

    // ---------- setup: per-point sampling data ----------
    {
        size_t base = ((size_t)r * Ns + tid) * 3;
        float nc[3];
#pragma unroll
        for (int k = 0; k < 3; k++) {
            float lo = aabb[k], hi = aabb[3 + k];
            nc[k] = (xyz[base + k] - lo) * (2.0f / (hi - lo)) - 1.0f;
        }
        s_z[tid] = zvals[(size_t)r * Ns + tid];

        const int MA[3] = {0, 0, 1}, MB[3] = {1, 2, 2}, MV[3] = {2, 1, 0};
        float stw3[3];
#pragma unroll
        for (int i = 0; i < 3; i++) {
            S1D sx = samp1d(nc[MA[i]], G);
            S1D sy = samp1d(nc[MB[i]], G);
            S1D st = samp1d(nc[MV[i]], G);
            // u00: f4-unit index incl. plane base; A = u00<<2 | dyb<<1 | dxb
            int u00 = i * (MAXHW * 8) + (sy.i0 * G + sx.i0) * 8;
            int A = (u00 << 2) | ((sy.i1 - sy.i0) << 1) | (sx.i1 - sx.i0);
            // taps: f4-unit indices incl. plane base, 16-bit each
            int t0u = i * (MAXG * 8) + st.i0 * 8;
            int t1u = i * (MAXG * 8) + st.i1 * 8;
            int T = t0u | (t1u << 16);
            s_setA[tid * 3 + i] = make_float4(
                __int_as_float(A), __int_as_float(T), sx.w, sy.w);
            stw3[i] = st.w;
        }
        s_setB[tid] = make_float4(stw3[0], stw3[1], stw3[2], 0.f);
    }
    __syncthreads();

    const ulonglong2* tbp = (const ulonglong2*)g_tex  + slot;   // stride 8/texel
    const ulonglong2* lbp = (const ulonglong2*)g_ltex + slot;

    // ---------- main pass: 32 points per warp ----------
    const int p0 = wrp << 5;
    for (int it = 0; it < 32; it++) {
        int p = p0 + it;
        float4 SB = s_setB[p];
        float stw3[3] = {SB.x, SB.y, SB.z};

        ull acc[4] = {0ull, 0ull, 0ull, 0ull};
#pragma unroll
        for (int i = 0; i < 3; i++) {
            float4 SA = s_setA[p * 3 + i];
            int A = __float_as_int(SA.x);
            int T = __float_as_int(SA.y);
            float sxw = SA.z, syw = SA.w;

            int u    = (unsigned)A >> 2;
            int ux   = (A & 1) << 3;
            int uyv  = (A & 2) ? G8 : 0;
            int offu = u + (pc1 ? ux : 0) + (pc2 ? uyv : 0);
            int t0u  = T & 0xFFFF;
            int t1u  = (unsigned)T >> 16;

            ulonglong2 tex = ldg_na(tbp + offu);   // streaming: no L1 alloc
            ulonglong2 l0  = __ldg(lbp + t0u);     // cached: L1-resident taps
            ulonglong2 l1  = __ldg(lbp + t1u);

            float wc = (pc1 ? sxw : 1.f - sxw) * (pc2 ? syw : 1.f - syw);
            float s1 = wc * stw3[i];
            float s0 = wc - s1;
            ull s0p = f2pk(s0, s0);
            ull s1p = f2pk(s1, s1);

            ull gA = mul2(tex.x, fma2(l1.x, s1p, mul2(l0.x, s0p)));
            ull gB = mul2(tex.y, fma2(l1.y, s1p, mul2(l0.y, s0p)));
#pragma unroll
            for (int rr = 0; rr < 4; rr++) {
                acc[rr] = fma2(gA, WA[rr][i], acc[rr]);
                acc[rr] = fma2(gB, WB[rr][i], acc[rr]);
            }
        }
        float2 a0 = f2un(acc[0]);
        float2 a1 = f2un(acc[1]);
        float2 a2 = f2un(acc[2]);
        float2 a3 = f2un(acc[3]);
        float v0 = a0.x + a0.y;
        float v1 = a1.x + a1.y;
        float v2 = a2.x + a2.y;
        float v3 = a3.x + a3.y;

        // 6-shuffle 4-output butterfly reduce; row r lands on lanes (lane&3)==r
        const int b0 = lane & 1;
        const int b1 = lane & 2;
        float s1v = b0 ? v0 : v1;
        float r1  = __shfl_xor_sync(0xffffffffu, s1v, 1);
        float u0  = (b0 ? v1 : v0) + r1;           // row b0
        float s2v = b0 ? v2 : v3;
        float r2  = __shfl_xor_sync(0xffffffffu, s2v, 1);
        float u1  = (b0 ? v3 : v2) + r2;           // row 2+b0
        float s3v = b1 ? u0 : u1;
        float r3  = __shfl_xor_sync(0xffffffffu, s3v, 2);
        float wv  = (b1 ? u1 : u0) + r3;           // row lane&3
        wv += __shfl_xor_sync(0xffffffffu, wv, 4);
        wv += __shfl_xor_sync(0xffffffffu, wv, 8);
        wv += __shfl_xor_sync(0xffffffffu, wv, 16);
        if (lane < 4) s_out[p * 4 + lane] = wv;
    }
    __syncthreads();

    // ---------- alpha + transmittance scan -> weights ----------
    float w;
    {
        float sfeat = s_out[tid * 4 + 3] - 10.0f;
        float sigma = (sfeat > 15.0f) ? sfeat : log1pf(expf(sfeat));
        float dist  = (tid < Ns - 1) ? (s_z[tid + 1] - s_z[tid])
                                     : (s_z[Ns - 1] - s_z[Ns - 2]);
        float alpha = -expm1f(-sigma * (dist * 25.0f));
        s_A[tid] = 1.0f - alpha + 1e-10f;
        __syncthreads();
        float* cur = s_A;
        float* nxt = s_B;
        for (int off = 1; off < Ns; off <<= 1) {
            float v = cur[tid];
            if (tid >= off) v *= cur[tid - off];
            nxt[tid] = v;
            __syncthreads();
            float* tmp = cur; cur = nxt; nxt = tmp;
        }
        float T = (tid == 0) ? 1.0f : cur[tid - 1];
        w = alpha * T;
    }

    // ---------- weighted rgb sum ----------
    float q0 = w * s_out[tid * 4 + 0];
    float q1 = w * s_out[tid * 4 + 1];
    float q2 = w * s_out[tid * 4 + 2];
#pragma unroll
    for (int m = 16; m > 0; m >>= 1) {
        q0 += __shfl_xor_sync(0xffffffffu, q0, m);
        q1 += __shfl_xor_sync(0xffffffffu, q1, m);
        q2 += __shfl_xor_sync(0xffffffffu, q2, m);
    }
    if (lane == 0) {
        s_part[wrp * 3 + 0] = q0;
        s_part[wrp * 3 + 1] = q1;
        s_part[wrp * 3 + 2] = q2;
    }
    __syncthreads();
    if (tid < 3) {
        float sum = 0.f;
#pragma unroll
        for (int ww = 0; ww < 8; ww++) sum += s_part[ww * 3 + tid];
        out[r * 3 + tid] = sum;
    }
}

extern "C" void kernel_launch(void* const* d_in, const int* in_sizes, int n_in,
                              void* d_out, int out_size) {
    const float* xyz   = (const float*)d_in[0];
    const float* zvals = (const float*)d_in[2];
    const float* dp    = (const float*)d_in[3];
    const float* dl    = (const float*)d_in[4];
    const float* ap    = (const float*)d_in[5];
    const float* al    = (const float*)d_in[6];
    const float* denw  = (const float*)d_in[7];
    const float* appw  = (const float*)d_in[8];
    const float* aabb  = (const float*)d_in[9];

    int Nr = in_sizes[1] / 3;
    int Ns = in_sizes[2] / Nr;
    int G  = in_sizes[4] / 24;
    int HW = G * G;

    int ntp = (HW + 127) / 128;
    int ntl = (G + 127) / 128;
    prep_kernel<<<3 * ntp + 3 * ntl, 256>>>(dp, ap, dl, al, denw, G);
    render_kernel<<<Nr, Ns>>>(xyz, zvals, appw, aabb, (float*)d_out, Ns, G);
}

// round 17
// speedup vs baseline: 1.7977x; 1.7977x over previous
#include <cuda_runtime.h>

// ---------------------------------------------------------------------------
// TensoRF slim renderer, v16 — pt-major lane mapping: lane = pt(4) x slot(8).
//  Processes 4 points per warp-iteration. Tap loads serve 4 points per LDG
//  (full-line utilization: tap wavefronts 24 -> 6 per point). Corner sum
//  computed BEFORE the line multiply ((sum_c wc_c tex_c) .* L . W), so the
//  8-fma2 row accumulate runs once per plane, not per corner. Each lane owns
//  its point's accumulators -> 8-lane butterfly reduce (1 shfl/pt vs 6).
//  prep: combined 128B fp32 texels g_tex[i][HW][32ch] (ch0-7 density, basis
//        weights folded into LINE texture; ch8-31 appearance), g_ltex lines.
//  Epilogue (scan, weights, rgb reduce) identical to the v8 champion.
// ---------------------------------------------------------------------------

#define MAXG  320
#define MAXHW (MAXG * MAXG)

__device__ float4 g_tex[3ull * MAXHW * 8];   // [i][p][8 float4] texel = 128B
__device__ float4 g_ltex[3 * MAXG * 8];      // [i][g][8 float4]

typedef unsigned long long ull;

__device__ __forceinline__ ull f2pk(float a, float b) {
    ull r; asm("mov.b64 %0,{%1,%2};" : "=l"(r) : "f"(a), "f"(b)); return r;
}
__device__ __forceinline__ float2 f2un(ull v) {
    float2 r; asm("mov.b64 {%0,%1},%2;" : "=f"(r.x), "=f"(r.y) : "l"(v)); return r;
}
__device__ __forceinline__ ull fma2(ull a, ull b, ull c) {
    ull r; asm("fma.rn.f32x2 %0,%1,%2,%3;" : "=l"(r) : "l"(a), "l"(b), "l"(c)); return r;
}
__device__ __forceinline__ ull mul2(ull a, ull b) {
    ull r; asm("mul.rn.f32x2 %0,%1,%2;" : "=l"(r) : "l"(a), "l"(b)); return r;
}

// ---------------- prep: interleave channels into 128B texels ----------------
__global__ void prep_kernel(const float* __restrict__ dp, const float* __restrict__ ap,
                            const float* __restrict__ dl, const float* __restrict__ al,
                            const float* __restrict__ denw, int G) {
    __shared__ float tile[32][129];
    int HW  = G * G;
    int ntp = (HW + 127) >> 7;
    int ntl = (G + 127) >> 7;
    int b = blockIdx.x;
    if (b < 3 * ntp) {
        int i = b / ntp, t = b - i * ntp;
        int p0 = t << 7;
        int np = min(128, HW - p0);
        for (int idx = threadIdx.x; idx < 32 * 128; idx += blockDim.x) {
            int ch = idx >> 7, p = idx & 127;
            float v = 0.f;
            if (p < np)
                v = (ch < 8) ? dp[(size_t)(i * 8 + ch) * HW + p0 + p]
                             : ap[(size_t)(i * 24 + ch - 8) * HW + p0 + p];
            tile[ch][p] = v;
        }
        __syncthreads();
        float* dst = (float*)(g_tex + ((size_t)i * MAXHW + p0) * 8);
        for (int idx = threadIdx.x; idx < np * 32; idx += blockDim.x) {
            int p = idx >> 5, ch = idx & 31;
            dst[idx] = tile[ch][p];
        }
    } else {
        b -= 3 * ntp;
        int i = b / ntl, t = b - i * ntl;
        int g0 = t << 7;
        int ng = min(128, G - g0);
        for (int idx = threadIdx.x; idx < 32 * 128; idx += blockDim.x) {
            int ch = idx >> 7, g = idx & 127;
            float v = 0.f;
            if (g < ng) {
                if (ch < 8) v = dl[(i * 8 + ch) * G + g0 + g] * denw[i * 8 + ch];
                else        v = al[(i * 24 + ch - 8) * G + g0 + g];
            }
            tile[ch][g] = v;
        }
        __syncthreads();
        float* dst = (float*)(g_ltex + ((size_t)i * MAXG + g0) * 8);
        for (int idx = threadIdx.x; idx < ng * 32; idx += blockDim.x) {
            int g = idx >> 5, ch = idx & 31;
            dst[idx] = tile[ch][g];
        }
    }
}

// ---------------- render ----------------
struct S1D { int i0, i1; float w; };

__device__ __forceinline__ S1D samp1d(float c, int G) {
    float f  = (c + 1.0f) * 0.5f * (float)(G - 1);
    float ff = floorf(f);
    S1D r;
    r.w = f - ff;                 // frac from UNclipped floor (matches ref)
    int i0 = (int)ff;
    i0 = min(max(i0, 0), G - 1);
    r.i0 = i0;
    r.i1 = min(i0 + 1, G - 1);
    return r;
}

__global__ __launch_bounds__(256, 3)
void render_kernel(const float* __restrict__ xyz,
                   const float* __restrict__ zvals,
                   const float* __restrict__ appw,
                   const float* __restrict__ aabb,
                   float* __restrict__ out,
                   int Ns, int G) {
    __shared__ float4 s_setA[256 * 3];  // per-pt per-plane (A, T, sxw, syw)
    __shared__ float4 s_setB[256];      // per-pt: stw x3
    __shared__ float  s_out[256 * 4];   // q0,q1,q2,sigma per point
    __shared__ float  s_z[256];
    __shared__ float  s_A[256];
    __shared__ float  s_B[256];
    __shared__ float  s_part[24];

    const int r      = blockIdx.x;
    const int tid    = threadIdx.x;
    const int lane   = tid & 31;
    const int wrp    = tid >> 5;
    const int t      = lane >> 3;       // point-within-quad 0..3
    const int slot   = lane & 7;        // 0..7 (f4 index within texel)
    const bool isApp = (slot >= 2);
    const int  G8    = G * 8;           // y-step in f4 units

    // packed weights: rows 0-2 = appw (zeros on density lanes);
    // row 3 = sigma row: ones on density lanes, zeros on app lanes.
    ull WA[4][3], WB[4][3];
    {
        const ull ones = f2pk(1.f, 1.f);
#pragma unroll
        for (int rr = 0; rr < 3; rr++)
#pragma unroll
            for (int i = 0; i < 3; i++) {
                if (isApp) {
                    float4 w = *(const float4*)(appw + rr * 72 + i * 24 + (slot - 2) * 4);
                    WA[rr][i] = f2pk(w.x, w.y);
                    WB[rr][i] = f2pk(w.z, w.w);
                } else {
                    WA[rr][i] = 0ull; WB[rr][i] = 0ull;
                }
            }
#pragma unroll
        for (int i = 0; i < 3; i++) {
            WA[3][i] = isApp ? 0ull : ones;
            WB[3][i] = isApp ? 0ull : ones;
        }
    }

    // ---------- setup: per-point sampling data (identical to v8) ----------
    {
        size_t base = ((size_t)r * Ns + tid) * 3;
        float nc[3];
#pragma unroll
        for (int k = 0; k < 3; k++) {
            float lo = aabb[k], hi = aabb[3 + k];
            nc[k] = (xyz[base + k] - lo) * (2.0f / (hi - lo)) - 1.0f;
        }
        s_z[tid] = zvals[(size_t)r * Ns + tid];

        const int MA[3] = {0, 0, 1}, MB[3] = {1, 2, 2}, MV[3] = {2, 1, 0};
        float stw3[3];
#pragma unroll
        for (int i = 0; i < 3; i++) {
            S1D sx = samp1d(nc[MA[i]], G);
            S1D sy = samp1d(nc[MB[i]], G);
            S1D st = samp1d(nc[MV[i]], G);
            // u00: f4-unit index incl. plane base; A = u00<<2 | dyb<<1 | dxb
            int u00 = i * (MAXHW * 8) + (sy.i0 * G + sx.i0) * 8;
            int A = (u00 << 2) | ((sy.i1 - sy.i0) << 1) | (sx.i1 - sx.i0);
            // taps: f4-unit indices incl. plane base, 16-bit each
            int t0u = i * (MAXG * 8) + st.i0 * 8;
            int t1u = i * (MAXG * 8) + st.i1 * 8;
            int T = t0u | (t1u << 16);
            s_setA[tid * 3 + i] = make_float4(
                __int_as_float(A), __int_as_float(T), sx.w, sy.w);
            stw3[i] = st.w;
        }
        s_setB[tid] = make_float4(stw3[0], stw3[1], stw3[2], 0.f);
    }
    __syncthreads();

    const ulonglong2* tbp = (const ulonglong2*)g_tex  + slot;   // stride 8/texel
    const ulonglong2* lbp = (const ulonglong2*)g_ltex + slot;

    // ---------- main pass: 4 points per iteration, 8 iterations ----------
    const int p0 = wrp << 5;
    for (int it = 0; it < 8; it++) {
        int p = p0 + (it << 2) + t;       // this lane's point
        float4 SB = s_setB[p];
        float stw3[3] = {SB.x, SB.y, SB.z};

        ull acc[4] = {0ull, 0ull, 0ull, 0ull};
#pragma unroll
        for (int i = 0; i < 3; i++) {
            float4 SA = s_setA[p * 3 + i];
            int A = __float_as_int(SA.x);
            int T = __float_as_int(SA.y);
            float sxw = SA.z, syw = SA.w;

            int u   = (unsigned)A >> 2;
            int ux  = (A & 1) << 3;
            int uyv = (A & 2) ? G8 : 0;
            int t0u = T & 0xFFFF;
            int t1u = (unsigned)T >> 16;

            // all 6 loads of this plane in flight
            ulonglong2 x0 = __ldg(tbp + u);
            ulonglong2 x1 = __ldg(tbp + u + ux);
            ulonglong2 x2 = __ldg(tbp + u + uyv);
            ulonglong2 x3 = __ldg(tbp + u + ux + uyv);
            ulonglong2 l0 = __ldg(lbp + t0u);
            ulonglong2 l1 = __ldg(lbp + t1u);

            // bilinear corner weights (scalars for THIS point)
            float wx1 = sxw, wx0 = 1.f - sxw;
            float wy1 = syw, wy0 = 1.f - syw;
            ull w00 = f2pk(wx0 * wy0, wx0 * wy0);
            ull w01 = f2pk(wx1 * wy0, wx1 * wy0);
            ull w10 = f2pk(wx0 * wy1, wx0 * wy1);
            ull w11 = f2pk(wx1 * wy1, wx1 * wy1);

            // corner sum first: S = sum_c wc_c * tex_c
            ull SxA = mul2(x0.x, w00);
            ull SxB = mul2(x0.y, w00);
            SxA = fma2(x1.x, w01, SxA);
            SxB = fma2(x1.y, w01, SxB);
            SxA = fma2(x2.x, w10, SxA);
            SxB = fma2(x2.y, w10, SxB);
            SxA = fma2(x3.x, w11, SxA);
            SxB = fma2(x3.y, w11, SxB);

            // tap lerp
            float s1 = stw3[i];
            float s0 = 1.f - s1;
            ull s0p = f2pk(s0, s0);
            ull s1p = f2pk(s1, s1);
            ull LA = fma2(l1.x, s1p, mul2(l0.x, s0p));
            ull LB = fma2(l1.y, s1p, mul2(l0.y, s0p));

            ull gA = mul2(SxA, LA);
            ull gB = mul2(SxB, LB);
#pragma unroll
            for (int rr = 0; rr < 4; rr++) {
                acc[rr] = fma2(gA, WA[rr][i], acc[rr]);
                acc[rr] = fma2(gB, WB[rr][i], acc[rr]);
            }
        }
        float2 a0 = f2un(acc[0]);
        float2 a1 = f2un(acc[1]);
        float2 a2 = f2un(acc[2]);
        float2 a3 = f2un(acc[3]);
        float v0 = a0.x + a0.y;
        float v1 = a1.x + a1.y;
        float v2 = a2.x + a2.y;
        float v3 = a3.x + a3.y;

        // 4-shuffle 4-output butterfly within each 8-lane point group;
        // row rr lands on lanes with (lane&3)==rr.
        const int b0 = lane & 1;
        const int b1 = lane & 2;
        float s1v = b0 ? v0 : v1;
        float r1  = __shfl_xor_sync(0xffffffffu, s1v, 1);
        float u0  = (b0 ? v1 : v0) + r1;           // row b0
        float s2v = b0 ? v2 : v3;
        float r2  = __shfl_xor_sync(0xffffffffu, s2v, 1);
        float u1  = (b0 ? v3 : v2) + r2;           // row 2+b0
        float s3v = b1 ? u0 : u1;
        float r3  = __shfl_xor_sync(0xffffffffu, s3v, 2);
        float wv  = (b1 ? u1 : u0) + r3;           // row lane&3
        wv += __shfl_xor_sync(0xffffffffu, wv, 4); // full 8-lane sum
        if (slot < 4) s_out[p * 4 + slot] = wv;
    }
    __syncthreads();

    // ---------- alpha + transmittance scan -> weights ----------
    float w;
    {
        float sfeat = s_out[tid * 4 + 3] - 10.0f;
        float sigma = (sfeat > 15.0f) ? sfeat : log1pf(expf(sfeat));
        float dist  = (tid < Ns - 1) ? (s_z[tid + 1] - s_z[tid])
                                     : (s_z[Ns - 1] - s_z[Ns - 2]);
        float alpha = -expm1f(-sigma * (dist * 25.0f));
        s_A[tid] = 1.0f - alpha + 1e-10f;
        __syncthreads();
        float* cur = s_A;
        float* nxt = s_B;
        for (int off = 1; off < Ns; off <<= 1) {
            float v = cur[tid];
            if (tid >= off) v *= cur[tid - off];
            nxt[tid] = v;
            __syncthreads();
            float* tmp = cur; cur = nxt; nxt = tmp;
        }
        float T = (tid == 0) ? 1.0f : cur[tid - 1];
        w = alpha * T;
    }

    // ---------- weighted rgb sum ----------
    float q0 = w * s_out[tid * 4 + 0];
    float q1 = w * s_out[tid * 4 + 1];
    float q2 = w * s_out[tid * 4 + 2];
#pragma unroll
    for (int m = 16; m > 0; m >>= 1) {
        q0 += __shfl_xor_sync(0xffffffffu, q0, m);
        q1 += __shfl_xor_sync(0xffffffffu, q1, m);
        q2 += __shfl_xor_sync(0xffffffffu, q2, m);
    }
    if (lane == 0) {
        s_part[wrp * 3 + 0] = q0;
        s_part[wrp * 3 + 1] = q1;
        s_part[wrp * 3 + 2] = q2;
    }
    __syncthreads();
    if (tid < 3) {
        float sum = 0.f;
#pragma unroll
        for (int ww = 0; ww < 8; ww++) sum += s_part[ww * 3 + tid];
        out[r * 3 + tid] = sum;
    }
}

extern "C" void kernel_launch(void* const* d_in, const int* in_sizes, int n_in,
                              void* d_out, int out_size) {
    const float* xyz   = (const float*)d_in[0];
    const float* zvals = (const float*)d_in[2];
    const float* dp    = (const float*)d_in[3];
    const float* dl    = (const float*)d_in[4];
    const float* ap    = (const float*)d_in[5];
    const float* al    = (const float*)d_in[6];
    const float* denw  = (const float*)d_in[7];
    const float* appw  = (const float*)d_in[8];
    const float* aabb  = (const float*)d_in[9];

    int Nr = in_sizes[1] / 3;
    int Ns = in_sizes[2] / Nr;
    int G  = in_sizes[4] / 24;
    int HW = G * G;

    int ntp = (HW + 127) / 128;
    int ntl = (G + 127) / 128;
    prep_kernel<<<3 * ntp + 3 * ntl, 256>>>(dp, ap, dl, al, denw, G);
    render_kernel<<<Nr, Ns>>>(xyz, zvals, appw, aabb, (float*)d_out, Ns, G);
}